// round 1
// baseline (speedup 1.0000x reference)
#include <cuda_runtime.h>
#include <cuda_bf16.h>
#include <math.h>

#define N_BINS 20
#define FULL_MASK 0xFFFFFFFFu

// Global scratch accumulators (allocation-free rule: __device__ globals)
__device__ double       g_conf_sum[N_BINS];
__device__ unsigned int g_cnt[N_BINS];
__device__ unsigned int g_acc[N_BINS];

__global__ void ece_zero_kernel() {
    int t = threadIdx.x;
    if (t < N_BINS) {
        g_conf_sum[t] = 0.0;
        g_cnt[t] = 0u;
        g_acc[t] = 0u;
    }
}

// One warp per row. Each lane loads float4 (lane*4 .. lane*4+3) -> 512B
// coalesced per row. Shuffle-reduce (max, first-argmax). Lane 0 bins the
// confidence and accumulates into shared; block flushes once to global.
__global__ __launch_bounds__(256) void ece_main_kernel(
    const float4* __restrict__ softmaxes,  // [N, 32] float4 view of [N,128]
    const int*    __restrict__ labels,
    int n)
{
    __shared__ float        s_conf[N_BINS];
    __shared__ unsigned int s_cnt[N_BINS];
    __shared__ unsigned int s_acc[N_BINS];

    int t = threadIdx.x;
    if (t < N_BINS) { s_conf[t] = 0.0f; s_cnt[t] = 0u; s_acc[t] = 0u; }
    __syncthreads();

    int lane    = t & 31;
    int warp    = (blockIdx.x * blockDim.x + t) >> 5;
    int nwarps  = (gridDim.x * blockDim.x) >> 5;

    for (int row = warp; row < n; row += nwarps) {
        float4 v = softmaxes[(long long)row * 32 + lane];

        // local max with first-occurrence index
        float m   = v.x;
        int   idx = lane * 4;
        if (v.y > m) { m = v.y; idx = lane * 4 + 1; }
        if (v.z > m) { m = v.z; idx = lane * 4 + 2; }
        if (v.w > m) { m = v.w; idx = lane * 4 + 3; }

        // warp reduce: max value, tie -> smaller index (first occurrence)
        #pragma unroll
        for (int off = 16; off > 0; off >>= 1) {
            float om = __shfl_down_sync(FULL_MASK, m,   off);
            int   oi = __shfl_down_sync(FULL_MASK, idx, off);
            if (om > m || (om == m && oi < idx)) { m = om; idx = oi; }
        }

        if (lane == 0) {
            // bin = clip(ceil(conf*20)-1, 0, 19)
            int b = (int)ceilf(m * (float)N_BINS) - 1;
            b = min(max(b, 0), N_BINS - 1);
            atomicAdd(&s_conf[b], m);
            atomicAdd(&s_cnt[b], 1u);
            if (idx == labels[row]) atomicAdd(&s_acc[b], 1u);
        }
    }

    __syncthreads();
    if (t < N_BINS) {
        unsigned int c = s_cnt[t];
        if (c) {
            atomicAdd(&g_conf_sum[t], (double)s_conf[t]);
            atomicAdd(&g_cnt[t], c);
            atomicAdd(&g_acc[t], s_acc[t]);
        }
    }
}

// Single-warp finalize: out[0] = ece, out[1..20] = ys
__global__ void ece_final_kernel(float* __restrict__ out, int n) {
    int b = threadIdx.x;  // 0..31
    float contrib = 0.0f;
    if (b < N_BINS) {
        unsigned int c = g_cnt[b];
        float y = 0.0f;
        if (c) {
            float avg_conf = (float)(g_conf_sum[b] / (double)c);
            float avg_acc  = (float)g_acc[b] / (float)c;
            float prop     = (float)c / (float)n;
            contrib = fabsf(avg_conf - avg_acc) * prop;
            y = avg_acc;
        }
        out[1 + b] = y;
    }
    #pragma unroll
    for (int off = 16; off > 0; off >>= 1)
        contrib += __shfl_down_sync(FULL_MASK, contrib, off);
    if (b == 0) out[0] = contrib;
}

extern "C" void kernel_launch(void* const* d_in, const int* in_sizes, int n_in,
                              void* d_out, int out_size) {
    const float* softmaxes = (const float*)d_in[0];
    const int*   labels    = (const int*)d_in[1];
    float*       out       = (float*)d_out;

    int n = in_sizes[1];              // number of rows = label count
    (void)n_in; (void)out_size;

    ece_zero_kernel<<<1, 32>>>();

    int threads = 256;
    int blocks  = 2048;               // 16384 warps, grid-stride over 1M rows
    ece_main_kernel<<<blocks, threads>>>((const float4*)softmaxes, labels, n);

    ece_final_kernel<<<1, 32>>>(out, n);
}

// round 3
// speedup vs baseline: 1.8861x; 1.8861x over previous
#include <cuda_runtime.h>
#include <cuda_bf16.h>
#include <math.h>

#define N_BINS 20
#define FULL_MASK 0xFFFFFFFFu

// Global scratch accumulators. Zero-initialized at module load; the finalize
// kernel re-zeroes them after reading, so every complete kernel_launch leaves
// them zeroed (deterministic across correctness run / capture / replays).
__device__ double       g_conf_sum[N_BINS];
__device__ unsigned int g_cnt[N_BINS];
__device__ unsigned int g_acc[N_BINS];

// Reduce one row held as per-lane uint bit patterns (positive floats: uint
// order == float order). Returns (conf_bits, argmax_idx) broadcast to all lanes.
__device__ __forceinline__ void row_reduce(unsigned int mbits, int midx,
                                           unsigned int& conf_bits, int& idx) {
    unsigned int wmax = __reduce_max_sync(FULL_MASK, mbits);
    unsigned int bal  = __ballot_sync(FULL_MASK, mbits == wmax);
    int wlane = __ffs(bal) - 1;                 // lowest lane -> first occurrence
    idx  = __shfl_sync(FULL_MASK, midx, wlane);
    conf_bits = wmax;
}

// Per-lane local max over its float4 (first-occurrence within the 4).
__device__ __forceinline__ void local_max4(float4 v, int lane,
                                           unsigned int& mbits, int& midx) {
    float m = v.x; int i = lane * 4;
    if (v.y > m) { m = v.y; i = lane * 4 + 1; }
    if (v.z > m) { m = v.z; i = lane * 4 + 2; }
    if (v.w > m) { m = v.w; i = lane * 4 + 3; }
    mbits = __float_as_uint(m); midx = i;
}

__global__ __launch_bounds__(256) void ece_main_kernel(
    const float4* __restrict__ softmaxes,  // [N, 32] float4 view of [N,128]
    const int*    __restrict__ labels,
    int n)
{
    __shared__ float        s_conf[N_BINS];
    __shared__ unsigned int s_cntacc[N_BINS];   // cnt in [0:16), correct in [16:32)

    int t = threadIdx.x;
    if (t < N_BINS) { s_conf[t] = 0.0f; s_cntacc[t] = 0u; }
    __syncthreads();

    int lane   = t & 31;
    int gwarp  = (blockIdx.x * blockDim.x + t) >> 5;
    int nwarps = (gridDim.x * blockDim.x) >> 5;

    int ngroups = n >> 2;    // groups of 4 rows

    for (int g = gwarp; g < ngroups; g += nwarps) {
        long long row0 = (long long)g << 2;
        const float4* p = softmaxes + row0 * 32 + lane;

        // 4 independent loads -> MLP=4
        float4 v0 = p[0];
        float4 v1 = p[32];
        float4 v2 = p[64];
        float4 v3 = p[96];
        int4 lab = ((const int4*)labels)[g];   // uniform across warp

        unsigned int b0, b1, b2, b3; int i0, i1, i2, i3;
        local_max4(v0, lane, b0, i0);
        local_max4(v1, lane, b1, i1);
        local_max4(v2, lane, b2, i2);
        local_max4(v3, lane, b3, i3);

        unsigned int c0, c1, c2, c3; int x0, x1, x2, x3;
        row_reduce(b0, i0, c0, x0);
        row_reduce(b1, i1, c1, x1);
        row_reduce(b2, i2, c2, x2);
        row_reduce(b3, i3, c3, x3);

        // lanes 0..3 each commit one row (all lanes hold all 4 results)
        if (lane < 4) {
            float conf; int idx; int label;
            if      (lane == 0) { conf = __uint_as_float(c0); idx = x0; label = lab.x; }
            else if (lane == 1) { conf = __uint_as_float(c1); idx = x1; label = lab.y; }
            else if (lane == 2) { conf = __uint_as_float(c2); idx = x2; label = lab.z; }
            else                { conf = __uint_as_float(c3); idx = x3; label = lab.w; }

            int b = (int)ceilf(conf * (float)N_BINS) - 1;
            b = min(max(b, 0), N_BINS - 1);
            unsigned int correct = (idx == label) ? 1u : 0u;
            atomicAdd(&s_conf[b], conf);
            atomicAdd(&s_cntacc[b], 1u | (correct << 16));
        }
    }

    // tail rows (n not divisible by 4) handled by warp 0
    if (gwarp == 0) {
        for (int row = ngroups << 2; row < n; row++) {
            float4 v = softmaxes[(long long)row * 32 + lane];
            unsigned int mb; int mi;
            local_max4(v, lane, mb, mi);
            unsigned int cb; int xi;
            row_reduce(mb, mi, cb, xi);
            if (lane == 0) {
                float conf = __uint_as_float(cb);
                int b = (int)ceilf(conf * (float)N_BINS) - 1;
                b = min(max(b, 0), N_BINS - 1);
                unsigned int correct = (xi == labels[row]) ? 1u : 0u;
                atomicAdd(&s_conf[b], conf);
                atomicAdd(&s_cntacc[b], 1u | (correct << 16));
            }
        }
    }

    __syncthreads();
    if (t < N_BINS) {
        unsigned int ca = s_cntacc[t];
        if (ca) {
            atomicAdd(&g_conf_sum[t], (double)s_conf[t]);
            atomicAdd(&g_cnt[t], ca & 0xFFFFu);
            atomicAdd(&g_acc[t], ca >> 16);
        }
    }
}

// Single-warp finalize: out[0] = ece, out[1..20] = ys. Self-cleans globals.
__global__ void ece_final_kernel(float* __restrict__ out, int n) {
    int b = threadIdx.x;  // 0..31
    float contrib = 0.0f;
    if (b < N_BINS) {
        unsigned int c = g_cnt[b];
        float y = 0.0f;
        if (c) {
            float avg_conf = (float)(g_conf_sum[b] / (double)c);
            float avg_acc  = (float)g_acc[b] / (float)c;
            float prop     = (float)c / (float)n;
            contrib = fabsf(avg_conf - avg_acc) * prop;
            y = avg_acc;
        }
        out[1 + b] = y;
        // reset for next launch (module-load state is also zero)
        g_conf_sum[b] = 0.0;
        g_cnt[b] = 0u;
        g_acc[b] = 0u;
    }
    #pragma unroll
    for (int off = 16; off > 0; off >>= 1)
        contrib += __shfl_down_sync(FULL_MASK, contrib, off);
    if (b == 0) out[0] = contrib;
}

extern "C" void kernel_launch(void* const* d_in, const int* in_sizes, int n_in,
                              void* d_out, int out_size) {
    const float* softmaxes = (const float*)d_in[0];
    const int*   labels    = (const int*)d_in[1];
    float*       out       = (float*)d_out;

    int n = in_sizes[1];              // number of rows = label count
    (void)n_in; (void)out_size;

    int threads = 256;
    int blocks  = 1216;               // ~one full wave on 152 SMs
    ece_main_kernel<<<blocks, threads>>>((const float4*)softmaxes, labels, n);

    ece_final_kernel<<<1, 32>>>(out, n);
}